// round 3
// baseline (speedup 1.0000x reference)
#include <cuda_runtime.h>
#include <cuda_bf16.h>
#include <cstdint>

#define NROWS 16384
#define KDIM  16384
#define NCOLS 64
#define KC    64
#define NCHUNK (KDIM / KC)

// -------- device scratch (no runtime allocs allowed) --------
__device__ __align__(256) float         g_sup[(size_t)NROWS * NCOLS];
__device__ __align__(256) __nv_bfloat16 g_shiT[(size_t)NCOLS * KDIM];
__device__ __align__(256) __nv_bfloat16 g_sloT[(size_t)NCOLS * KDIM];

// -------- helpers --------
__device__ __forceinline__ uint32_t smem_u32(const void* p) {
    uint32_t a;
    asm("{ .reg .u64 t; cvta.to.shared.u64 t, %1; cvt.u32.u64 %0, t; }" : "=r"(a) : "l"(p));
    return a;
}
__device__ __forceinline__ uint32_t sw128(uint32_t off) { return off ^ ((off >> 3) & 0x70); }

// pack2(a,b): bf16x2 with a in LOW halfword (rn)
__device__ __forceinline__ uint32_t pack2(float a, float b) {
    uint32_t r;
    asm("cvt.rn.bf16x2.f32 %0, %1, %2;" : "=r"(r) : "f"(b), "f"(a));
    return r;
}
__device__ __forceinline__ float2 unpack2(uint32_t u) {
    __nv_bfloat162 h = *reinterpret_cast<__nv_bfloat162*>(&u);
    return make_float2(__low2float(h), __high2float(h));
}
__device__ __forceinline__ void sts128(uint32_t addr, uint32_t a, uint32_t b, uint32_t c, uint32_t d) {
    asm volatile("st.shared.v4.b32 [%0], {%1,%2,%3,%4};"
                 :: "r"(addr), "r"(a), "r"(b), "r"(c), "r"(d) : "memory");
}

#define LDSM4(r, addr) \
    asm volatile("ldmatrix.sync.aligned.m8n8.x4.shared.b16 {%0,%1,%2,%3}, [%4];" \
                 : "=r"((r)[0]), "=r"((r)[1]), "=r"((r)[2]), "=r"((r)[3]) : "r"(addr))

#define MMA16816(d, a, b0_, b1_) \
    asm volatile("mma.sync.aligned.m16n8k16.row.col.f32.bf16.bf16.f32 " \
                 "{%0,%1,%2,%3}, {%4,%5,%6,%7}, {%8,%9}, {%0,%1,%2,%3};" \
                 : "+f"((d)[0]), "+f"((d)[1]), "+f"((d)[2]), "+f"((d)[3]) \
                 : "r"((a)[0]), "r"((a)[1]), "r"((a)[2]), "r"((a)[3]), \
                   "r"(b0_), "r"(b1_))

// -------- prep: support = x @ W ; store fp32 + transposed bf16 hi/lo --------
__global__ __launch_bounds__(256) void gcn_prep(const float* __restrict__ x,
                                                const float* __restrict__ W) {
    int tid = threadIdx.x;
    int rg = tid & 31, cg = tid >> 5;
    int row0 = blockIdx.x * 128 + rg * 4;
    int c0 = cg * 8;
    float acc[4][8];
#pragma unroll
    for (int i = 0; i < 4; i++)
#pragma unroll
        for (int j = 0; j < 8; j++) acc[i][j] = 0.f;

    const float4* x4 = reinterpret_cast<const float4*>(x);  // row pitch 64 float4
    const float4* W4 = reinterpret_cast<const float4*>(W);  // row pitch 16 float4

    for (int k4 = 0; k4 < 64; k4++) {
        float4 xv[4];
#pragma unroll
        for (int i = 0; i < 4; i++) xv[i] = __ldg(&x4[(size_t)(row0 + i) * 64 + k4]);
#pragma unroll
        for (int j = 0; j < 4; j++) {
            float4 wa = __ldg(&W4[(k4 * 4 + j) * 16 + cg * 2]);
            float4 wb = __ldg(&W4[(k4 * 4 + j) * 16 + cg * 2 + 1]);
#pragma unroll
            for (int i = 0; i < 4; i++) {
                float xs = (j == 0) ? xv[i].x : (j == 1) ? xv[i].y : (j == 2) ? xv[i].z : xv[i].w;
                acc[i][0] = fmaf(xs, wa.x, acc[i][0]);
                acc[i][1] = fmaf(xs, wa.y, acc[i][1]);
                acc[i][2] = fmaf(xs, wa.z, acc[i][2]);
                acc[i][3] = fmaf(xs, wa.w, acc[i][3]);
                acc[i][4] = fmaf(xs, wb.x, acc[i][4]);
                acc[i][5] = fmaf(xs, wb.y, acc[i][5]);
                acc[i][6] = fmaf(xs, wb.z, acc[i][6]);
                acc[i][7] = fmaf(xs, wb.w, acc[i][7]);
            }
        }
    }
#pragma unroll
    for (int i = 0; i < 4; i++) {
        float* sp = g_sup + (size_t)(row0 + i) * NCOLS + c0;
        reinterpret_cast<float4*>(sp)[0] = make_float4(acc[i][0], acc[i][1], acc[i][2], acc[i][3]);
        reinterpret_cast<float4*>(sp)[1] = make_float4(acc[i][4], acc[i][5], acc[i][6], acc[i][7]);
    }
#pragma unroll
    for (int j = 0; j < 8; j++) {
        int c = c0 + j;
        uint32_t h0 = pack2(acc[0][j], acc[1][j]);
        uint32_t h1 = pack2(acc[2][j], acc[3][j]);
        float2 f0 = unpack2(h0), f1 = unpack2(h1);
        uint32_t l0 = pack2(acc[0][j] - f0.x, acc[1][j] - f0.y);
        uint32_t l1 = pack2(acc[2][j] - f1.x, acc[3][j] - f1.y);
        size_t off = (size_t)c * KDIM + row0;
        *reinterpret_cast<uint2*>(g_shiT + off) = make_uint2(h0, h1);
        *reinterpret_cast<uint2*>(g_sloT + off) = make_uint2(l0, l1);
    }
}

// -------- main: out = relu(adj @ support + support + b) --------
// 128 CTAs x 128 rows, 256 threads. Warp grid 4(m) x 2(n); 32x32 out per warp.
#define STAGE_BYTES 49152   // A_hi 16K | A_lo 16K | B_hi 8K | B_lo 8K
#define SMEM_MAIN   (1024 + 2 * STAGE_BYTES)

__global__ __launch_bounds__(256, 1) void gcn_main(const float* __restrict__ adj,
                                                   const float* __restrict__ bias,
                                                   float* __restrict__ out) {
    extern __shared__ char dsm[];
    uint32_t tiles = (smem_u32(dsm) + 1023) & ~1023u;
    int tid = threadIdx.x;
    int wid = tid >> 5;
    int lane = tid & 31;
    int row0 = blockIdx.x * 128;
    int wm = wid & 3, wn = wid >> 2;

    // loader mapping
    int arow = tid >> 1, ahalf = tid & 1;
    int brow = tid >> 2, bq = tid & 3;

    // ldmatrix per-lane offsets
    uint32_t a_r  = ((lane >> 3) & 1) * 8 + (lane & 7);   // row within m16
    uint32_t a_kh = (lane >> 4) & 1;                      // k half (8 elems)
    uint32_t b_r  = ((lane >> 4) & 1) * 8 + (lane & 7);   // row within n16 pair
    uint32_t b_kh = (lane >> 3) & 1;

    uint32_t arowb[2], browb[2];
#pragma unroll
    for (int mt = 0; mt < 2; mt++) arowb[mt] = (wm * 32 + mt * 16 + a_r) * 128;
#pragma unroll
    for (int p = 0; p < 2; p++)   browb[p]  = (wn * 32 + p * 16 + b_r) * 128;

    float acc[2][4][4];
#pragma unroll
    for (int mt = 0; mt < 2; mt++)
#pragma unroll
        for (int nt = 0; nt < 4; nt++)
#pragma unroll
            for (int j = 0; j < 4; j++) acc[mt][nt][j] = 0.f;

    // ---- prologue: stage chunk 0 ----
    {
        uint32_t A_hi = tiles, A_lo = tiles + 16384, B_hi = tiles + 32768, B_lo = tiles + 40960;
        float4 av[8];
        const float4* ap = reinterpret_cast<const float4*>(
            adj + (size_t)(row0 + arow) * KDIM + ahalf * 32);
#pragma unroll
        for (int q = 0; q < 8; q++) av[q] = ap[q];
        const uint4* bhp = reinterpret_cast<const uint4*>(g_shiT + (size_t)brow * KDIM);
        const uint4* blp = reinterpret_cast<const uint4*>(g_sloT + (size_t)brow * KDIM);
        uint4 bh0 = bhp[bq], bh1 = bhp[bq + 4], bl0 = blp[bq], bl1 = blp[bq + 4];

        const float* f = reinterpret_cast<const float*>(av);
        uint32_t abase = (uint32_t)arow * 128 + (uint32_t)ahalf * 64;
#pragma unroll
        for (int q = 0; q < 4; q++) {
            uint32_t wh[4], wl[4];
#pragma unroll
            for (int i = 0; i < 4; i++) {
                float a0 = f[q * 8 + 2 * i], a1 = f[q * 8 + 2 * i + 1];
                wh[i] = pack2(a0, a1);
                float2 h = unpack2(wh[i]);
                wl[i] = pack2(a0 - h.x, a1 - h.y);
            }
            uint32_t off = sw128(abase + q * 16);
            sts128(A_hi + off, wh[0], wh[1], wh[2], wh[3]);
            sts128(A_lo + off, wl[0], wl[1], wl[2], wl[3]);
        }
        uint32_t o0 = sw128((uint32_t)brow * 128 + (uint32_t)bq * 16);
        uint32_t o1 = sw128((uint32_t)brow * 128 + (uint32_t)(bq + 4) * 16);
        sts128(B_hi + o0, bh0.x, bh0.y, bh0.z, bh0.w);
        sts128(B_hi + o1, bh1.x, bh1.y, bh1.z, bh1.w);
        sts128(B_lo + o0, bl0.x, bl0.y, bl0.z, bl0.w);
        sts128(B_lo + o1, bl1.x, bl1.y, bl1.z, bl1.w);
    }
    __syncthreads();

    // ---- main loop ----
#pragma unroll 1
    for (int c = 0; c < NCHUNK; ++c) {
        int st = c & 1;
        uint32_t A_hi = tiles + st * STAGE_BYTES;
        uint32_t A_lo = A_hi + 16384;
        uint32_t B_hi = A_hi + 32768;
        uint32_t B_lo = A_hi + 40960;

        // prefetch A of chunk c+1 (HBM) before MMA to hide latency
        float4 av[8];
        bool more = (c + 1 < NCHUNK);
        if (more) {
            const float4* ap = reinterpret_cast<const float4*>(
                adj + (size_t)(row0 + arow) * KDIM + (c + 1) * KC + ahalf * 32);
#pragma unroll
            for (int q = 0; q < 8; q++) av[q] = ap[q];
        }

        // MMA over this chunk (reads stage st)
#pragma unroll
        for (int ks = 0; ks < 4; ks++) {
            uint32_t ak = (uint32_t)(ks * 32) + a_kh * 16;   // bytes: (ks*16 + kh*8)*2
            uint32_t bk = (uint32_t)(ks * 32) + b_kh * 16;
            uint32_t ah[2][4], al[2][4], bh[2][4], bl[2][4];
#pragma unroll
            for (int mt = 0; mt < 2; mt++) {
                LDSM4(ah[mt], A_hi + sw128(arowb[mt] + ak));
                LDSM4(al[mt], A_lo + sw128(arowb[mt] + ak));
            }
#pragma unroll
            for (int p = 0; p < 2; p++) {
                LDSM4(bh[p], B_hi + sw128(browb[p] + bk));
                LDSM4(bl[p], B_lo + sw128(browb[p] + bk));
            }
#pragma unroll
            for (int mt = 0; mt < 2; mt++) {
#pragma unroll
                for (int nt = 0; nt < 4; nt++) {
                    int p = nt >> 1, h = (nt & 1) * 2;
                    MMA16816(acc[mt][nt], ah[mt], bh[p][h], bh[p][h + 1]);
                    MMA16816(acc[mt][nt], ah[mt], bl[p][h], bl[p][h + 1]);
                    MMA16816(acc[mt][nt], al[mt], bh[p][h], bh[p][h + 1]);
                }
            }
        }

        // stage chunk c+1 into stage st^1
        if (more) {
            const uint4* bhp = reinterpret_cast<const uint4*>(
                g_shiT + (size_t)brow * KDIM + (c + 1) * KC);
            const uint4* blp = reinterpret_cast<const uint4*>(
                g_sloT + (size_t)brow * KDIM + (c + 1) * KC);
            uint4 bh0 = bhp[bq], bh1 = bhp[bq + 4], bl0 = blp[bq], bl1 = blp[bq + 4];

            uint32_t Ah2 = tiles + (st ^ 1) * STAGE_BYTES;
            uint32_t Al2 = Ah2 + 16384, Bh2 = Ah2 + 32768, Bl2 = Ah2 + 40960;
            const float* f = reinterpret_cast<const float*>(av);
            uint32_t abase = (uint32_t)arow * 128 + (uint32_t)ahalf * 64;
#pragma unroll
            for (int q = 0; q < 4; q++) {
                uint32_t wh[4], wl[4];
#pragma unroll
                for (int i = 0; i < 4; i++) {
                    float a0 = f[q * 8 + 2 * i], a1 = f[q * 8 + 2 * i + 1];
                    wh[i] = pack2(a0, a1);
                    float2 h2 = unpack2(wh[i]);
                    wl[i] = pack2(a0 - h2.x, a1 - h2.y);
                }
                uint32_t off = sw128(abase + q * 16);
                sts128(Ah2 + off, wh[0], wh[1], wh[2], wh[3]);
                sts128(Al2 + off, wl[0], wl[1], wl[2], wl[3]);
            }
            uint32_t o0 = sw128((uint32_t)brow * 128 + (uint32_t)bq * 16);
            uint32_t o1 = sw128((uint32_t)brow * 128 + (uint32_t)(bq + 4) * 16);
            sts128(Bh2 + o0, bh0.x, bh0.y, bh0.z, bh0.w);
            sts128(Bh2 + o1, bh1.x, bh1.y, bh1.z, bh1.w);
            sts128(Bl2 + o0, bl0.x, bl0.y, bl0.z, bl0.w);
            sts128(Bl2 + o1, bl1.x, bl1.y, bl1.z, bl1.w);
        }
        __syncthreads();
    }

    // ---- epilogue: out = relu(acc + support + bias) ----
    int g = lane >> 2, t = lane & 3;
#pragma unroll
    for (int mt = 0; mt < 2; mt++) {
        int ra = row0 + wm * 32 + mt * 16 + g;
#pragma unroll
        for (int nt = 0; nt < 4; nt++) {
            int col = wn * 32 + nt * 8 + t * 2;
            float2 bb = *reinterpret_cast<const float2*>(bias + col);
            float2 s0 = *reinterpret_cast<const float2*>(g_sup + (size_t)ra * NCOLS + col);
            float2 s1 = *reinterpret_cast<const float2*>(g_sup + (size_t)(ra + 8) * NCOLS + col);
            float2 r0, r1;
            r0.x = fmaxf(acc[mt][nt][0] + s0.x + bb.x, 0.f);
            r0.y = fmaxf(acc[mt][nt][1] + s0.y + bb.y, 0.f);
            r1.x = fmaxf(acc[mt][nt][2] + s1.x + bb.x, 0.f);
            r1.y = fmaxf(acc[mt][nt][3] + s1.y + bb.y, 0.f);
            *reinterpret_cast<float2*>(out + (size_t)ra * NCOLS + col) = r0;
            *reinterpret_cast<float2*>(out + (size_t)(ra + 8) * NCOLS + col) = r1;
        }
    }
}

extern "C" void kernel_launch(void* const* d_in, const int* in_sizes, int n_in,
                              void* d_out, int out_size) {
    const float *x = nullptr, *adj = nullptr, *W = nullptr, *b = nullptr;
    for (int i = 0; i < n_in; i++) {
        long s = in_sizes[i];
        if (s == (long)NROWS * 256)        x   = (const float*)d_in[i];
        else if (s == (long)NROWS * NROWS) adj = (const float*)d_in[i];
        else if (s == 256L * NCOLS)        W   = (const float*)d_in[i];
        else if (s == (long)NCOLS)         b   = (const float*)d_in[i];
    }
    cudaFuncSetAttribute(gcn_main, cudaFuncAttributeMaxDynamicSharedMemorySize, SMEM_MAIN);
    gcn_prep<<<128, 256>>>(x, W);
    gcn_main<<<128, 256, SMEM_MAIN>>>(adj, b, (float*)d_out);
}

// round 4
// speedup vs baseline: 1.3039x; 1.3039x over previous
#include <cuda_runtime.h>
#include <cuda_bf16.h>
#include <cstdint>

#define NROWS 16384
#define KDIM  16384
#define NCOLS 64
#define KC    64
#define NCHUNK (KDIM / KC)

// -------- device scratch (no runtime allocs allowed) --------
__device__ __align__(256) float         g_sup[(size_t)NROWS * NCOLS];
__device__ __align__(256) __nv_bfloat16 g_shiT[(size_t)NCOLS * KDIM];
__device__ __align__(256) __nv_bfloat16 g_sloT[(size_t)NCOLS * KDIM];

// -------- helpers --------
__device__ __forceinline__ uint32_t smem_u32(const void* p) {
    uint32_t a;
    asm("{ .reg .u64 t; cvta.to.shared.u64 t, %1; cvt.u32.u64 %0, t; }" : "=r"(a) : "l"(p));
    return a;
}
__device__ __forceinline__ uint32_t sw128(uint32_t off) { return off ^ ((off >> 3) & 0x70); }

// pack2(a,b): bf16x2 with a in LOW halfword (rn)
__device__ __forceinline__ uint32_t pack2(float a, float b) {
    uint32_t r;
    asm("cvt.rn.bf16x2.f32 %0, %1, %2;" : "=r"(r) : "f"(b), "f"(a));
    return r;
}
__device__ __forceinline__ float2 unpack2(uint32_t u) {
    __nv_bfloat162 h = *reinterpret_cast<__nv_bfloat162*>(&u);
    return make_float2(__low2float(h), __high2float(h));
}
// high bf16 halves of two floats packed (truncation split)
__device__ __forceinline__ uint32_t prmt_hi(uint32_t u0, uint32_t u1) {
    uint32_t r;
    asm("prmt.b32 %0, %1, %2, 0x7632;" : "=r"(r) : "r"(u0), "r"(u1));
    return r;
}
__device__ __forceinline__ void sts128(uint32_t addr, uint32_t a, uint32_t b, uint32_t c, uint32_t d) {
    asm volatile("st.shared.v4.b32 [%0], {%1,%2,%3,%4};"
                 :: "r"(addr), "r"(a), "r"(b), "r"(c), "r"(d) : "memory");
}

#define LDSM4(r, addr) \
    asm volatile("ldmatrix.sync.aligned.m8n8.x4.shared.b16 {%0,%1,%2,%3}, [%4];" \
                 : "=r"((r)[0]), "=r"((r)[1]), "=r"((r)[2]), "=r"((r)[3]) : "r"(addr))

#define MMA16816(d, a, b0_, b1_) \
    asm volatile("mma.sync.aligned.m16n8k16.row.col.f32.bf16.bf16.f32 " \
                 "{%0,%1,%2,%3}, {%4,%5,%6,%7}, {%8,%9}, {%0,%1,%2,%3};" \
                 : "+f"((d)[0]), "+f"((d)[1]), "+f"((d)[2]), "+f"((d)[3]) \
                 : "r"((a)[0]), "r"((a)[1]), "r"((a)[2]), "r"((a)[3]), \
                   "r"(b0_), "r"(b1_))

// -------- prep: support = x @ W ; store fp32 + transposed bf16 hi/lo --------
__global__ __launch_bounds__(256) void gcn_prep(const float* __restrict__ x,
                                                const float* __restrict__ W) {
    int tid = threadIdx.x;
    int rg = tid & 31, cg = tid >> 5;
    int row0 = blockIdx.x * 128 + rg * 4;
    int c0 = cg * 8;
    float acc[4][8];
#pragma unroll
    for (int i = 0; i < 4; i++)
#pragma unroll
        for (int j = 0; j < 8; j++) acc[i][j] = 0.f;

    const float4* x4 = reinterpret_cast<const float4*>(x);
    const float4* W4 = reinterpret_cast<const float4*>(W);

    for (int k4 = 0; k4 < 64; k4++) {
        float4 xv[4];
#pragma unroll
        for (int i = 0; i < 4; i++) xv[i] = __ldg(&x4[(size_t)(row0 + i) * 64 + k4]);
#pragma unroll
        for (int j = 0; j < 4; j++) {
            float4 wa = __ldg(&W4[(k4 * 4 + j) * 16 + cg * 2]);
            float4 wb = __ldg(&W4[(k4 * 4 + j) * 16 + cg * 2 + 1]);
#pragma unroll
            for (int i = 0; i < 4; i++) {
                float xs = (j == 0) ? xv[i].x : (j == 1) ? xv[i].y : (j == 2) ? xv[i].z : xv[i].w;
                acc[i][0] = fmaf(xs, wa.x, acc[i][0]);
                acc[i][1] = fmaf(xs, wa.y, acc[i][1]);
                acc[i][2] = fmaf(xs, wa.z, acc[i][2]);
                acc[i][3] = fmaf(xs, wa.w, acc[i][3]);
                acc[i][4] = fmaf(xs, wb.x, acc[i][4]);
                acc[i][5] = fmaf(xs, wb.y, acc[i][5]);
                acc[i][6] = fmaf(xs, wb.z, acc[i][6]);
                acc[i][7] = fmaf(xs, wb.w, acc[i][7]);
            }
        }
    }
#pragma unroll
    for (int i = 0; i < 4; i++) {
        float* sp = g_sup + (size_t)(row0 + i) * NCOLS + c0;
        reinterpret_cast<float4*>(sp)[0] = make_float4(acc[i][0], acc[i][1], acc[i][2], acc[i][3]);
        reinterpret_cast<float4*>(sp)[1] = make_float4(acc[i][4], acc[i][5], acc[i][6], acc[i][7]);
    }
#pragma unroll
    for (int j = 0; j < 8; j++) {
        int c = c0 + j;
        uint32_t h0 = pack2(acc[0][j], acc[1][j]);
        uint32_t h1 = pack2(acc[2][j], acc[3][j]);
        float2 f0 = unpack2(h0), f1 = unpack2(h1);
        uint32_t l0 = pack2(acc[0][j] - f0.x, acc[1][j] - f0.y);
        uint32_t l1 = pack2(acc[2][j] - f1.x, acc[3][j] - f1.y);
        size_t off = (size_t)c * KDIM + row0;
        *reinterpret_cast<uint2*>(g_shiT + off) = make_uint2(h0, h1);
        *reinterpret_cast<uint2*>(g_sloT + off) = make_uint2(l0, l1);
    }
}

// -------- main: out = relu(adj @ support + support + b) --------
// 128 CTAs x 128 rows, 512 threads (16 warps: 4m x 4n, 32x16 tile each).
#define STAGE_BYTES 49152   // A_hi 16K | A_lo 16K | B_hi 8K | B_lo 8K
#define SMEM_MAIN   (1024 + 2 * STAGE_BYTES)

struct AStage { float f[16]; };

__device__ __forceinline__ void stage_A(uint32_t A_hi, uint32_t A_lo,
                                        const float* f, uint32_t abase) {
    const uint32_t* u = reinterpret_cast<const uint32_t*>(f);
#pragma unroll
    for (int q = 0; q < 2; q++) {
        uint32_t wh[4], wl[4];
#pragma unroll
        for (int i = 0; i < 4; i++) {
            uint32_t u0 = u[q * 8 + 2 * i], u1 = u[q * 8 + 2 * i + 1];
            wh[i] = prmt_hi(u0, u1);
            float l0 = f[q * 8 + 2 * i]     - __uint_as_float(u0 & 0xFFFF0000u);
            float l1 = f[q * 8 + 2 * i + 1] - __uint_as_float(u1 & 0xFFFF0000u);
            wl[i] = pack2(l0, l1);
        }
        uint32_t off = sw128(abase + q * 16);
        sts128(A_hi + off, wh[0], wh[1], wh[2], wh[3]);
        sts128(A_lo + off, wl[0], wl[1], wl[2], wl[3]);
    }
}

__global__ __launch_bounds__(512, 1) void gcn_main(const float* __restrict__ adj,
                                                   const float* __restrict__ bias,
                                                   float* __restrict__ out) {
    extern __shared__ char dsm[];
    uint32_t tiles = (smem_u32(dsm) + 1023) & ~1023u;
    int tid = threadIdx.x;
    int wid = tid >> 5;
    int lane = tid & 31;
    int row0 = blockIdx.x * 128;
    int wm = wid & 3, wn = wid >> 2;

    // loader mapping
    int arow = tid >> 2, aseg = tid & 3;   // A: 128 rows x 4 segs of 16 floats
    int brow = tid >> 3, bq = tid & 7;     // B: 64 rows x 8 segs of 16 bytes
    uint32_t abase = (uint32_t)arow * 128 + (uint32_t)aseg * 32;
    uint32_t boff  = sw128((uint32_t)brow * 128 + (uint32_t)bq * 16);

    // ldmatrix per-lane offsets
    uint32_t a_r  = ((lane >> 3) & 1) * 8 + (lane & 7);
    uint32_t a_kh = (lane >> 4) & 1;
    uint32_t b_r  = ((lane >> 4) & 1) * 8 + (lane & 7);
    uint32_t b_kh = (lane >> 3) & 1;

    uint32_t arowb[2];
#pragma unroll
    for (int mt = 0; mt < 2; mt++) arowb[mt] = (wm * 32 + mt * 16 + a_r) * 128;
    uint32_t browb = (wn * 16 + b_r) * 128;

    float acc[2][2][4];
#pragma unroll
    for (int mt = 0; mt < 2; mt++)
#pragma unroll
        for (int nt = 0; nt < 2; nt++)
#pragma unroll
            for (int j = 0; j < 4; j++) acc[mt][nt][j] = 0.f;

    const float4* apbase = reinterpret_cast<const float4*>(
        adj + (size_t)(row0 + arow) * KDIM + aseg * 16);

    // ---- prologue: stage chunk 0 ----
    {
        AStage av;
#pragma unroll
        for (int q = 0; q < 4; q++)
            reinterpret_cast<float4*>(av.f)[q] = apbase[q];
        uint4 bh = reinterpret_cast<const uint4*>(g_shiT + (size_t)brow * KDIM)[bq];
        uint4 bl = reinterpret_cast<const uint4*>(g_sloT + (size_t)brow * KDIM)[bq];
        stage_A(tiles, tiles + 16384, av.f, abase);
        sts128(tiles + 32768 + boff, bh.x, bh.y, bh.z, bh.w);
        sts128(tiles + 40960 + boff, bl.x, bl.y, bl.z, bl.w);
    }
    __syncthreads();

    // ---- main loop ----
#pragma unroll 1
    for (int c = 0; c < NCHUNK; ++c) {
        int st = c & 1;
        uint32_t A_hi = tiles + st * STAGE_BYTES;
        uint32_t A_lo = A_hi + 16384;
        uint32_t B_hi = A_hi + 32768;
        uint32_t B_lo = A_hi + 40960;

        // prefetch chunk c+1 (A from HBM, B from L2) before MMA
        AStage av;
        uint4 bhn, bln;
        bool more = (c + 1 < NCHUNK);
        if (more) {
            const float4* ap = apbase + (size_t)(c + 1) * (KC / 4);
#pragma unroll
            for (int q = 0; q < 4; q++)
                reinterpret_cast<float4*>(av.f)[q] = ap[q];
            bhn = reinterpret_cast<const uint4*>(
                g_shiT + (size_t)brow * KDIM + (c + 1) * KC)[bq];
            bln = reinterpret_cast<const uint4*>(
                g_sloT + (size_t)brow * KDIM + (c + 1) * KC)[bq];
        }

        // MMA over this chunk
#pragma unroll
        for (int ks = 0; ks < 4; ks++) {
            uint32_t ak = (uint32_t)(ks * 32) + a_kh * 16;
            uint32_t bk = (uint32_t)(ks * 32) + b_kh * 16;
            uint32_t ah[2][4], al[2][4], bh[4], bl[4];
#pragma unroll
            for (int mt = 0; mt < 2; mt++) {
                LDSM4(ah[mt], A_hi + sw128(arowb[mt] + ak));
                LDSM4(al[mt], A_lo + sw128(arowb[mt] + ak));
            }
            LDSM4(bh, B_hi + sw128(browb + bk));
            LDSM4(bl, B_lo + sw128(browb + bk));
#pragma unroll
            for (int mt = 0; mt < 2; mt++) {
#pragma unroll
                for (int nt = 0; nt < 2; nt++) {
                    int h = nt * 2;
                    MMA16816(acc[mt][nt], ah[mt], bh[h], bh[h + 1]);
                    MMA16816(acc[mt][nt], ah[mt], bl[h], bl[h + 1]);
                    MMA16816(acc[mt][nt], al[mt], bh[h], bh[h + 1]);
                }
            }
        }

        // stage chunk c+1
        if (more) {
            uint32_t Ah2 = tiles + (st ^ 1) * STAGE_BYTES;
            stage_A(Ah2, Ah2 + 16384, av.f, abase);
            sts128(Ah2 + 32768 + boff, bhn.x, bhn.y, bhn.z, bhn.w);
            sts128(Ah2 + 40960 + boff, bln.x, bln.y, bln.z, bln.w);
        }
        __syncthreads();
    }

    // ---- epilogue: out = relu(acc + support + bias) ----
    int g = lane >> 2, t = lane & 3;
#pragma unroll
    for (int mt = 0; mt < 2; mt++) {
        int ra = row0 + wm * 32 + mt * 16 + g;
#pragma unroll
        for (int nt = 0; nt < 2; nt++) {
            int col = wn * 16 + nt * 8 + t * 2;
            float2 bb = *reinterpret_cast<const float2*>(bias + col);
            float2 s0 = *reinterpret_cast<const float2*>(g_sup + (size_t)ra * NCOLS + col);
            float2 s1 = *reinterpret_cast<const float2*>(g_sup + (size_t)(ra + 8) * NCOLS + col);
            float2 r0, r1;
            r0.x = fmaxf(acc[mt][nt][0] + s0.x + bb.x, 0.f);
            r0.y = fmaxf(acc[mt][nt][1] + s0.y + bb.y, 0.f);
            r1.x = fmaxf(acc[mt][nt][2] + s1.x + bb.x, 0.f);
            r1.y = fmaxf(acc[mt][nt][3] + s1.y + bb.y, 0.f);
            *reinterpret_cast<float2*>(out + (size_t)ra * NCOLS + col) = r0;
            *reinterpret_cast<float2*>(out + (size_t)(ra + 8) * NCOLS + col) = r1;
        }
    }
}

extern "C" void kernel_launch(void* const* d_in, const int* in_sizes, int n_in,
                              void* d_out, int out_size) {
    const float *x = nullptr, *adj = nullptr, *W = nullptr, *b = nullptr;
    for (int i = 0; i < n_in; i++) {
        long s = in_sizes[i];
        if (s == (long)NROWS * 256)        x   = (const float*)d_in[i];
        else if (s == (long)NROWS * NROWS) adj = (const float*)d_in[i];
        else if (s == 256L * NCOLS)        W   = (const float*)d_in[i];
        else if (s == (long)NCOLS)         b   = (const float*)d_in[i];
    }
    cudaFuncSetAttribute(gcn_main, cudaFuncAttributeMaxDynamicSharedMemorySize, SMEM_MAIN);
    gcn_prep<<<128, 256>>>(x, W);
    gcn_main<<<128, 512, SMEM_MAIN>>>(adj, b, (float*)d_out);
}